// round 14
// baseline (speedup 1.0000x reference)
#include <cuda_runtime.h>
#include <cuda_bf16.h>
#include <math.h>
#include <stdint.h>

#define NCTA 148
#define NT   512
#define BB   2048
#define DD   256
#define HH   266
#define HP   272
#define SS   50
#define EPSBN 1e-5f
#define SIGMA_C 0.3f
#define KC   96

// smem layout (bytes); row stride 104 halfs (208B)
#define ABUF(b)  ((b) * 26624)          // A: 128 rows x 104 halfs (bf16)
#define BBUF(b)  (53248 + (b) * 13312)  // B: 32 rows x 104 halfs, hi+lo
#define BLO      6656
#define OF_SC    79872
#define OF_SH    81024
#define SMEM_DYN 82176

// ---------------- device scratch ----------------
__device__ float g_X[BB * DD];
__device__ __nv_bfloat16 g_Xhi[BB * DD];
__device__ float g_Y1[BB * HP];
__device__ float g_Y2[BB * HP];
__device__ float g_Yv3[BB];
__device__ __nv_bfloat16 g_Wt1hi[SS * HH * DD], g_Wt1lo[SS * HH * DD];
__device__ __nv_bfloat16 g_Wt2hi[SS * HH * HP], g_Wt2lo[SS * HH * HP];
__device__ __nv_bfloat16 g_Wt3hi[SS * DD * HP], g_Wt3lo[SS * DD * HP];
__device__ __nv_bfloat16 g_Wv1hi[HH * DD], g_Wv1lo[HH * DD];
__device__ __nv_bfloat16 g_Wv2hi[HH * HP], g_Wv2lo[HH * HP];
__device__ __nv_bfloat16 g_Wv3hi[HP],      g_Wv3lo[HP];
__device__ float g_S1[HP], g_Q1[HP], g_S2[HP], g_Q2[HP], g_SC[1], g_QC[1];
__device__ volatile unsigned g_arr[NCTA];
__device__ volatile unsigned g_rel;
__device__ volatile unsigned g_done;

// ---------------- PTX helpers ----------------
__device__ __forceinline__ uint32_t smem_u32(const void* p) {
    uint32_t a;
    asm("{ .reg .u64 t; cvta.to.shared.u64 t, %1; cvt.u32.u64 %0, t; }" : "=r"(a) : "l"(p));
    return a;
}
#define LDSM4(r, addr) \
    asm volatile("ldmatrix.sync.aligned.m8n8.x4.shared.b16 {%0,%1,%2,%3}, [%4];" \
        : "=r"((r)[0]), "=r"((r)[1]), "=r"((r)[2]), "=r"((r)[3]) : "r"(addr))
#define MMA16816(c, a, b0_, b1_) \
    asm volatile("mma.sync.aligned.m16n8k16.row.col.f32.bf16.bf16.f32 " \
        "{%0,%1,%2,%3}, {%4,%5,%6,%7}, {%8,%9}, {%0,%1,%2,%3};" \
        : "+f"((c)[0]), "+f"((c)[1]), "+f"((c)[2]), "+f"((c)[3]) \
        : "r"((a)[0]), "r"((a)[1]), "r"((a)[2]), "r"((a)[3]), "r"(b0_), "r"(b1_))
#define CP16(dst, src) \
    asm volatile("cp.async.ca.shared.global [%0], [%1], 16;" :: "r"(dst), "l"(src) : "memory")
#define CP_COMMIT() asm volatile("cp.async.commit_group;" ::: "memory")
#define CP_WAIT0()  asm volatile("cp.async.wait_group 0;" ::: "memory")

// flag-tree grid barrier: no atomic contention
__device__ __forceinline__ void gridbar(unsigned& ep) {
    __syncthreads();
    ep++;
    const int tid = threadIdx.x;
    if (blockIdx.x == 0) {
        if (tid == 0) { __threadfence(); g_arr[0] = ep; }
        if (tid >= 1 && tid < NCTA) { while (g_arr[tid] < ep) { } }
        __syncthreads();
        if (tid == 0) { g_rel = ep; __threadfence(); }
    } else if (tid == 0) {
        __threadfence();
        g_arr[blockIdx.x] = ep;
        while (g_rel < ep) { }
        __threadfence();
    }
    __syncthreads();
}

// ---------------- transpose + split (weights keep hi+lo) ----------------
__device__ void tsplit(const float* __restrict__ src, int K, int N,
                       __nv_bfloat16* __restrict__ dh, __nv_bfloat16* __restrict__ dl,
                       int ldT, float (*ts)[33]) {
    int ktiles = (ldT + 31) >> 5, ntiles = (N + 31) >> 5;
    for (int t = 0; t < ktiles * ntiles; t++) {
        int kt = t / ntiles, nt = t - kt * ntiles;
        int k0 = kt << 5, n0 = nt << 5;
        __syncthreads();
        #pragma unroll
        for (int s2 = 0; s2 < 2; s2++) {
            int idx = s2 * NT + threadIdx.x;
            int r = idx >> 5, c = idx & 31;
            int k = k0 + r, n = n0 + c;
            ts[r][c] = (k < K && n < N) ? src[(size_t)k * N + n] : 0.f;
        }
        __syncthreads();
        #pragma unroll
        for (int s2 = 0; s2 < 2; s2++) {
            int idx = s2 * NT + threadIdx.x;
            int rr = idx >> 5, cc = idx & 31;
            int n = n0 + rr, k = k0 + cc;
            if (n < N && k < ldT) {
                float v = ts[cc][rr];
                __nv_bfloat16 hb = __float2bfloat16(v);
                dh[(size_t)n * ldT + k] = hb;
                dl[(size_t)n * ldT + k] = __float2bfloat16(v - __bfloat162float(hb));
            }
        }
    }
}

// ---------------- HMMA GEMM phase (128x32 tile, 16 warps, pipelined) --------
template<int MODE, bool BN, bool ASPLIT>
__device__ __noinline__ void mma_gemm(char* alp, uint32_t sbase,
    int rowBase, int cb, bool preB,
    const float* __restrict__ A, int ldA, int K, int Ksteps,
    const __nv_bfloat16* __restrict__ Ahs,
    const __nv_bfloat16* __restrict__ Bh, const __nv_bfloat16* __restrict__ Bl, int Nout,
    const float* __restrict__ bias,
    const float* __restrict__ bng, const float* __restrict__ bnb,
    const float* __restrict__ ssum, const float* __restrict__ ssq,
    float* __restrict__ C, int ldc, float* osum, float* osq,
    float hstep, float cstep, float* __restrict__ V,
    float* __restrict__ X, const float* __restrict__ dWi, const float* __restrict__ lawi)
{
    const int tid = threadIdx.x;
    const int lane = tid & 31;
    const int warp = tid >> 5;
    const int mr = warp & 7;
    const int nc = warp >> 3;
    float* scK = (float*)(alp + OF_SC);
    float* shK = (float*)(alp + OF_SH);

    const int nch = (Ksteps + KC - 1) / KC;
    float fa[24];

    auto ldAreg = [&](int ch) {
        const int k0 = ch * KC;
        #pragma unroll
        for (int it = 0; it < 3; it++) {
            int idx = it * NT + tid;
            int row = idx / 12, kg = idx - row * 12;
            int gk = k0 + kg * 8;
            if (gk < Ksteps) {
                const float* ap = A + (size_t)(rowBase + row) * ldA + gk;
                float4 v0 = *(const float4*)ap;
                float4 v1 = *(const float4*)(ap + 4);
                fa[it*8+0] = v0.x; fa[it*8+1] = v0.y; fa[it*8+2] = v0.z; fa[it*8+3] = v0.w;
                fa[it*8+4] = v1.x; fa[it*8+5] = v1.y; fa[it*8+6] = v1.z; fa[it*8+7] = v1.w;
            } else {
                #pragma unroll
                for (int e = 0; e < 8; e++) fa[it*8+e] = 0.f;
            }
        }
    };
    auto stA = [&](int ch, int buf) {
        const int k0 = ch * KC;
        #pragma unroll
        for (int it = 0; it < 3; it++) {
            int idx = it * NT + tid;
            int row = idx / 12, kg = idx - row * 12;
            int gk = k0 + kg * 8;
            union { __nv_bfloat16 h[8]; uint4 u; } th;
            if (gk < Ksteps) {
                #pragma unroll
                for (int e = 0; e < 8; e++) {
                    float v = fa[it*8+e];
                    if (BN) v = fmaxf(fmaf(v, scK[gk + e], shK[gk + e]), 0.f);
                    th.h[e] = __float2bfloat16(v);
                }
            } else th.u = make_uint4(0, 0, 0, 0);
            uint32_t off = (uint32_t)(row * 104 + kg * 8) * 2u;
            *(uint4*)(alp + ABUF(buf) + off) = th.u;
        }
    };
    auto cpA = [&](int ch, int buf) {
        const int k0 = ch * KC;
        #pragma unroll
        for (int it = 0; it < 3; it++) {
            int idx = it * NT + tid;
            int row = idx / 12, kg = idx - row * 12;
            int gk = k0 + kg * 8;
            if (gk < Ksteps) {
                uint32_t off = (uint32_t)(row * 104 + kg * 8) * 2u;
                CP16(sbase + ABUF(buf) + off, Ahs + (size_t)(rowBase + row) * ldA + gk);
            }
        }
    };
    auto cpB = [&](int ch, int buf) {
        if (tid < 384) {
            const int k0 = ch * KC;
            int row = tid / 12, kg = tid - row * 12;
            int gk = k0 + kg * 8;
            int n = cb + row;
            uint32_t off = (uint32_t)(row * 104 + kg * 8) * 2u;
            uint32_t d0 = sbase + BBUF(buf) + off;
            if (gk < Ksteps && n < Nout) {
                CP16(d0, Bh + (size_t)n * Ksteps + gk);
                CP16(d0 + BLO, Bl + (size_t)n * Ksteps + gk);
            } else {
                uint4 z = make_uint4(0, 0, 0, 0);
                *(uint4*)(alp + BBUF(buf) + off) = z;
                *(uint4*)(alp + BBUF(buf) + BLO + off) = z;
            }
        }
    };

    float acc[2][4] = {};
    uint32_t ahf[2][4], bhf[2][4], blf[2][4];
    const uint32_t aoOff = 2u * (uint32_t)((mr * 16 + (lane & 15)) * 104 + ((lane >> 4) << 3));
    const uint32_t boOff = 2u * (uint32_t)((nc * 16 + (lane & 7) + ((lane >> 3) & 1) * 8) * 104
                                           + ((lane >> 4) << 3));

    // prologue: global loads first; BN table overlaps them
    if (ASPLIT) { cpA(0, 0); if (!preB) cpB(0, 0); CP_COMMIT(); }
    else        { ldAreg(0); if (!preB) cpB(0, 0); CP_COMMIT(); }
    if (BN) {
        const float invB = 1.f / (float)BB;
        for (int k = tid; k < HP; k += NT) {
            if (k < K) {
                float mu  = ssum[k] * invB;
                float var = ssq[k] * invB - mu * mu;
                float rstd = rsqrtf(var + EPSBN);
                float sc = bng[k] * rstd;
                scK[k] = sc; shK[k] = bnb[k] - mu * sc;
            } else { scK[k] = 0.f; shK[k] = 0.f; }
        }
    }
    __syncthreads();
    if (!ASPLIT) stA(0, 0);
    CP_WAIT0();
    __syncthreads();

    for (int ch = 0; ch < nch; ch++) {
        const int buf = ch & 1;
        const bool more = (ch + 1 < nch);
        if (more) {
            if (ASPLIT) cpA(ch + 1, buf ^ 1);
            else        ldAreg(ch + 1);
            cpB(ch + 1, buf ^ 1); CP_COMMIT();
        }

        int ns = (Ksteps - ch * KC) >> 4; if (ns > KC / 16) ns = KC / 16;
        uint32_t ao = sbase + ABUF(buf) + aoOff;
        uint32_t bo = sbase + BBUF(buf) + boOff;
        LDSM4(ahf[0], ao); LDSM4(bhf[0], bo); LDSM4(blf[0], bo + BLO);
        for (int kk = 0; kk < ns; kk++) {
            const int p = kk & 1;
            if (kk + 1 < ns) {
                uint32_t a2 = ao + (kk + 1) * 32, b2 = bo + (kk + 1) * 32;
                LDSM4(ahf[p ^ 1], a2); LDSM4(bhf[p ^ 1], b2); LDSM4(blf[p ^ 1], b2 + BLO);
            }
            #pragma unroll
            for (int t = 0; t < 2; t++) {
                MMA16816(acc[t], ahf[p], bhf[p][t], bhf[p][t + 2]);
                MMA16816(acc[t], ahf[p], blf[p][t], blf[p][t + 2]);
            }
        }

        if (more && !ASPLIT) stA(ch + 1, buf ^ 1);
        CP_WAIT0();
        __syncthreads();
    }

    // ---- fragments -> Cs [128][36] raw ----
    float* Cs = (float*)alp;
    {
        int r0 = mr * 16 + (lane >> 2);
        #pragma unroll
        for (int t = 0; t < 2; t++) {
            int cl = nc * 16 + t * 8 + (lane & 3) * 2;
            Cs[r0 * 36 + cl]           = acc[t][0];
            Cs[r0 * 36 + cl + 1]       = acc[t][1];
            Cs[(r0 + 8) * 36 + cl]     = acc[t][2];
            Cs[(r0 + 8) * 36 + cl + 1] = acc[t][3];
        }
    }
    __syncthreads();

    if (MODE == 0) {
        float* red2 = (float*)(alp + 20480);
        #pragma unroll
        for (int it = 0; it < 8; it++) {
            int idx = it * NT + tid;
            int row = idx >> 5, col = idx & 31;
            int gn = cb + col;
            if (gn < Nout)
                C[(size_t)(rowBase + row) * ldc + gn] = Cs[row * 36 + col] + bias[gn];
        }
        {
            int col = tid & 31, seg = tid >> 5;
            float s = 0.f, q = 0.f;
            #pragma unroll
            for (int r8 = 0; r8 < 8; r8++) {
                float v = Cs[(seg * 8 + r8) * 36 + col];
                s += v; q += v * v;
            }
            red2[seg * 32 + col] = s;
            red2[512 + seg * 32 + col] = q;
        }
        __syncthreads();
        if (tid < 32) {
            float s = 0.f, q = 0.f;
            #pragma unroll
            for (int g = 0; g < 16; g++) { s += red2[g * 32 + tid]; q += red2[512 + g * 32 + tid]; }
            int gn = cb + tid;
            if (gn < Nout) {
                float b = bias[gn];
                atomicAdd(&osum[gn], s + 128.f * b);
                atomicAdd(&osq[gn], q + 2.f * b * s + 128.f * b * b);
            }
        }
        __syncthreads();
    } else if (MODE == 1) {
        int row = tid >> 2, quad = tid & 3;
        size_t rbo = (size_t)(rowBase + row) * DD + cb + quad * 8;
        float p1 = 0.f, p2 = 0.f, p3 = 0.f;
        float xr[8];
        #pragma unroll
        for (int j4 = 0; j4 < 2; j4++) {
            int cl = quad * 8 + j4 * 4;
            int gc = cb + cl;
            float4 bj = *(const float4*)(bias + gc);
            float4 xv = *(const float4*)(X + rbo + j4 * 4);
            float4 dv = *(const float4*)(dWi + rbo + j4 * 4);
            float4 lw = *(const float4*)(lawi + gc);
            float q0 = Cs[row * 36 + cl]     + bj.x;
            float q1 = Cs[row * 36 + cl + 1] + bj.y;
            float q2 = Cs[row * 36 + cl + 2] + bj.z;
            float q3 = Cs[row * 36 + cl + 3] + bj.w;
            float n0 = cstep * dv.x, n1 = cstep * dv.y;
            float n2 = cstep * dv.z, n3 = cstep * dv.w;
            float d0 = xv.x - lw.x, d1 = xv.y - lw.y;
            float d2 = xv.z - lw.z, d3 = xv.w - lw.w;
            p1 += d0 * d0 + d1 * d1 + d2 * d2 + d3 * d3;
            p2 += q0 * q0 + q1 * q1 + q2 * q2 + q3 * q3;
            p3 += q0 * n0 + q1 * n1 + q2 * n2 + q3 * n3;
            float4 xo;
            xo.x = xv.x - q0 * hstep + n0;
            xo.y = xv.y - q1 * hstep + n1;
            xo.z = xv.z - q2 * hstep + n2;
            xo.w = xv.w - q3 * hstep + n3;
            *(float4*)(X + rbo + j4 * 4) = xo;
            xr[j4*4+0] = xo.x; xr[j4*4+1] = xo.y; xr[j4*4+2] = xo.z; xr[j4*4+3] = xo.w;
        }
        {
            union { __nv_bfloat16 h[8]; uint4 u; } th;
            #pragma unroll
            for (int e = 0; e < 8; e++) th.h[e] = __float2bfloat16(xr[e]);
            *(uint4*)(g_Xhi + rbo) = th.u;
        }
        float t = -0.5f * hstep * (p1 + p2) + p3;
        t += __shfl_down_sync(0xffffffffu, t, 1);
        t += __shfl_down_sync(0xffffffffu, t, 2);
        if ((lane & 3) == 0) atomicAdd(&V[rowBase + row], t);
        __syncthreads();
    } else {
        if (tid < 128) {
            float v = Cs[tid * 36] + bias[0];
            g_Yv3[rowBase + tid] = v;
            float s = v, q = v * v;
            #pragma unroll
            for (int o = 16; o > 0; o >>= 1) {
                s += __shfl_down_sync(0xffffffffu, s, o);
                q += __shfl_down_sync(0xffffffffu, q, o);
            }
            if ((tid & 31) == 0) { atomicAdd(&g_SC[0], s); atomicAdd(&g_QC[0], q); }
        }
        __syncthreads();
    }
}

// ---------------- single persistent kernel ----------------
extern "C" __global__ void __launch_bounds__(NT, 1)
mega_kernel(const float* __restrict__ x, const float* __restrict__ dW,
            const float* __restrict__ law, const float* __restrict__ tg,
            const float* __restrict__ W1, const float* __restrict__ b1,
            const float* __restrict__ g1, const float* __restrict__ be1,
            const float* __restrict__ W2, const float* __restrict__ b2,
            const float* __restrict__ g2, const float* __restrict__ be2,
            const float* __restrict__ W3, const float* __restrict__ b3,
            const float* __restrict__ Wv1, const float* __restrict__ bv1,
            const float* __restrict__ gv1, const float* __restrict__ bev1,
            const float* __restrict__ Wv2, const float* __restrict__ bv2,
            const float* __restrict__ gv2, const float* __restrict__ bev2,
            const float* __restrict__ Wv3, const float* __restrict__ bv3,
            const float* __restrict__ gv3, const float* __restrict__ bev3,
            float* __restrict__ V)
{
    extern __shared__ char dsm[];
    const int cta = blockIdx.x;
    const int tid = threadIdx.x;
    char* alp = dsm;
    uint32_t sbase = smem_u32(dsm);
    unsigned ep = 0;
    const int rb = (cta & 15) * 128;
    const int cb = (cta >> 4) * 32;

    // prefetch chunk-0 B of the NEXT phase into buf0 (before barrier arrive)
    auto prefB = [&](const __nv_bfloat16* Bh, const __nv_bfloat16* Bl, int Ksteps, int Nout) {
        if (tid < 384) {
            int row = tid / 12, kg = tid - row * 12;
            int gk = kg * 8;
            int n = cb + row;
            uint32_t off = (uint32_t)(row * 104 + kg * 8) * 2u;
            uint32_t d0 = sbase + BBUF(0) + off;
            if (gk < Ksteps && n < Nout) {
                CP16(d0, Bh + (size_t)n * Ksteps + gk);
                CP16(d0 + BLO, Bl + (size_t)n * Ksteps + gk);
            } else {
                uint4 z = make_uint4(0, 0, 0, 0);
                *(uint4*)(alp + BBUF(0) + off) = z;
                *(uint4*)(alp + BBUF(0) + BLO + off) = z;
            }
        }
        CP_COMMIT();
    };

    if (cta == 0) {
        for (int j = tid; j < HP; j += NT) { g_S1[j] = 0.f; g_Q1[j] = 0.f; g_S2[j] = 0.f; g_Q2[j] = 0.f; }
        if (tid == 0) { g_SC[0] = 0.f; g_QC[0] = 0.f; }
    }
    {   // copy X and convert to bf16
        for (int idx = cta * NT + tid; idx < BB * DD / 4; idx += NCTA * NT)
            ((float4*)g_X)[idx] = ((const float4*)x)[idx];
        int idx8 = cta * NT + tid;
        if (idx8 < BB * DD / 8) {
            const float* xp = x + idx8 * 8;
            union { __nv_bfloat16 h[8]; uint4 u; } th;
            #pragma unroll
            for (int e = 0; e < 8; e++) th.h[e] = __float2bfloat16(xp[e]);
            *(uint4*)(g_Xhi + (size_t)idx8 * 8) = th.u;
        }
    }
    {
        float (*ts)[33] = (float (*)[33])alp;
        for (int m = cta; m < 153; m += NCTA) {
            if (m < 50)
                tsplit(W1 + (size_t)m * DD * HH, DD, HH,
                       g_Wt1hi + (size_t)m * HH * DD, g_Wt1lo + (size_t)m * HH * DD, DD, ts);
            else if (m < 100)
                tsplit(W2 + (size_t)(m - 50) * HH * HH, HH, HH,
                       g_Wt2hi + (size_t)(m - 50) * HH * HP, g_Wt2lo + (size_t)(m - 50) * HH * HP, HP, ts);
            else if (m < 150)
                tsplit(W3 + (size_t)(m - 100) * HH * DD, HH, DD,
                       g_Wt3hi + (size_t)(m - 100) * DD * HP, g_Wt3lo + (size_t)(m - 100) * DD * HP, HP, ts);
            else if (m == 150) tsplit(Wv1, DD, HH, g_Wv1hi, g_Wv1lo, DD, ts);
            else if (m == 151) tsplit(Wv2, HH, HH, g_Wv2hi, g_Wv2lo, HP, ts);
            else               tsplit(Wv3, HH, 1,  g_Wv3hi, g_Wv3lo, HP, ts);
        }
    }
    gridbar(ep);

    // v0 L1
    if (cta < 144)
        mma_gemm<0, false, true>(alp, sbase, rb, cb, false,
            0, DD, 256, 256, g_Xhi, g_Wv1hi, g_Wv1lo, HH, bv1,
            0, 0, 0, 0, g_Y1, HP, g_S1, g_Q1, 0, 0, 0, 0, 0, 0);
    gridbar(ep);
    // v0 L2
    if (cta < 144)
        mma_gemm<0, true, false>(alp, sbase, rb, cb, false,
            g_Y1, HP, 266, 272, 0, g_Wv2hi, g_Wv2lo, HH, bv2,
            gv1, bev1, g_S1, g_Q1, g_Y2, HP, g_S2, g_Q2, 0, 0, 0, 0, 0, 0);
    gridbar(ep);
    // v0 L3 (N=1)
    if (cta < 16)
        mma_gemm<2, true, false>(alp, sbase, cta * 128, 0, false,
            g_Y2, HP, 266, 272, 0, g_Wv3hi, g_Wv3lo, 1, bv3,
            gv2, bev2, g_S2, g_Q2, 0, 0, 0, 0, 0, 0, 0, 0, 0, 0);
    else if (cta == 100)
        for (int j = tid; j < HP; j += NT) { g_S1[j] = 0.f; g_Q1[j] = 0.f; }
    gridbar(ep);
    // v0 finalize + prefetch step-0 L1 B
    {
        int r = cta * NT + tid;
        if (r < BB) {
            float invB = 1.f / (float)BB;
            float mu  = g_SC[0] * invB;
            float var = g_QC[0] * invB - mu * mu;
            float rstd = rsqrtf(var + EPSBN);
            V[r] = fmaxf(gv3[0] * (g_Yv3[r] - mu) * rstd + bev3[0], 0.f);
        }
        if (cta == 8)
            for (int j = tid; j < HP; j += NT) { g_S2[j] = 0.f; g_Q2[j] = 0.f; }
    }
    if (cta < 144) prefB(g_Wt1hi, g_Wt1lo, 256, HH);
    gridbar(ep);

    #pragma unroll 1
    for (int i = 0; i < SS; i++) {
        float h  = tg[i + 1] - tg[i];
        float cs = SIGMA_C * sqrtf(h);
        // L1: Xbf16 -> Y1 + S1/Q1   (B prefetched)
        if (cta < 144) {
            mma_gemm<0, false, true>(alp, sbase, rb, cb, true,
                0, DD, 256, 256, g_Xhi,
                g_Wt1hi + (size_t)i * HH * DD, g_Wt1lo + (size_t)i * HH * DD, HH,
                b1 + (size_t)i * HH, 0, 0, 0, 0,
                g_Y1, HP, g_S1, g_Q1, 0, 0, 0, 0, 0, 0);
            prefB(g_Wt2hi + (size_t)i * HH * HP, g_Wt2lo + (size_t)i * HH * HP, 272, HH);
        } else if (cta == 147)
            for (int j = tid; j < HP; j += NT) { g_S2[j] = 0.f; g_Q2[j] = 0.f; }
        gridbar(ep);
        // L2: BN(Y1) -> Y2 + S2/Q2   (B prefetched)
        if (cta < 144) {
            mma_gemm<0, true, false>(alp, sbase, rb, cb, true,
                g_Y1, HP, 266, 272, 0,
                g_Wt2hi + (size_t)i * HH * HP, g_Wt2lo + (size_t)i * HH * HP, HH,
                b2 + (size_t)i * HH, g1 + (size_t)i * HH, be1 + (size_t)i * HH, g_S1, g_Q1,
                g_Y2, HP, g_S2, g_Q2, 0, 0, 0, 0, 0, 0);
            if (cta < 128)
                prefB(g_Wt3hi + (size_t)i * DD * HP, g_Wt3lo + (size_t)i * DD * HP, 272, DD);
            else if (i + 1 < SS)
                prefB(g_Wt1hi + (size_t)(i + 1) * HH * DD, g_Wt1lo + (size_t)(i + 1) * HH * DD, 256, HH);
        }
        gridbar(ep);
        // L3: BN(Y2) -> grad; fused SDE update + X bf16   (B prefetched)
        if (cta < 128) {
            mma_gemm<1, true, false>(alp, sbase, rb, cb, true,
                g_Y2, HP, 266, 272, 0,
                g_Wt3hi + (size_t)i * DD * HP, g_Wt3lo + (size_t)i * DD * HP, DD,
                b3 + (size_t)i * DD, g2 + (size_t)i * HH, be2 + (size_t)i * HH, g_S2, g_Q2,
                0, 0, 0, 0, h, cs, V, g_X, dW + (size_t)i * BB * DD, law + (size_t)i * DD);
            if (i + 1 < SS)
                prefB(g_Wt1hi + (size_t)(i + 1) * HH * DD, g_Wt1lo + (size_t)(i + 1) * HH * DD, 256, HH);
        } else if (cta == 144)
            for (int j = tid; j < HP; j += NT) { g_S1[j] = 0.f; g_Q1[j] = 0.f; }
        gridbar(ep);
    }

    // reset barrier state for next launch
    if (tid == 0) {
        g_arr[cta] = 0;
        __threadfence();
        atomicAdd((unsigned*)&g_done, 1u);
        if (cta == 0) {
            while (g_done < NCTA) { }
            g_rel = 0;
            __threadfence();
            g_done = 0;
        }
    }
}

// ---------------- host launcher ----------------
extern "C" void kernel_launch(void* const* d_in, const int* in_sizes, int n_in,
                              void* d_out, int out_size)
{
    cudaFuncSetAttribute((const void*)mega_kernel,
                         cudaFuncAttributeMaxDynamicSharedMemorySize, SMEM_DYN);
    mega_kernel<<<NCTA, NT, SMEM_DYN>>>(
        (const float*)d_in[0], (const float*)d_in[1], (const float*)d_in[2], (const float*)d_in[3],
        (const float*)d_in[4],  (const float*)d_in[5],  (const float*)d_in[6],  (const float*)d_in[7],
        (const float*)d_in[8],  (const float*)d_in[9],  (const float*)d_in[10], (const float*)d_in[11],
        (const float*)d_in[12], (const float*)d_in[13],
        (const float*)d_in[14], (const float*)d_in[15], (const float*)d_in[16], (const float*)d_in[17],
        (const float*)d_in[18], (const float*)d_in[19], (const float*)d_in[20], (const float*)d_in[21],
        (const float*)d_in[22], (const float*)d_in[23], (const float*)d_in[24], (const float*)d_in[25],
        (float*)d_out);
    (void)in_sizes; (void)n_in; (void)out_size;
}

// round 15
// speedup vs baseline: 1.1571x; 1.1571x over previous
#include <cuda_runtime.h>
#include <cuda_bf16.h>
#include <math.h>
#include <stdint.h>

#define NCTA 148
#define NT   512
#define BB   2048
#define DD   256
#define HH   266
#define HP   272
#define SS   50
#define EPSBN 1e-5f
#define SIGMA_C 0.3f
#define KC   96

// smem layout (bytes)
#define OF_A     0                       // A: 128 rows x 280 halfs (bf16) = 71680
#define BBUF(b)  (71680 + (b) * 13312)   // B: 32 rows x 104 halfs, hi+lo
#define BLO      6656
#define OF_SC    98304
#define OF_SH    99456
#define SMEM_DYN 100608

// ---------------- device scratch ----------------
__device__ float g_X[BB * DD];
__device__ __nv_bfloat16 g_Xhi[BB * DD];
__device__ __nv_bfloat16 g_Y1b[BB * HP];
__device__ __nv_bfloat16 g_Y2b[BB * HP];
__device__ float g_Yv3[BB];
__device__ __nv_bfloat16 g_Wt1hi[SS * HH * DD], g_Wt1lo[SS * HH * DD];
__device__ __nv_bfloat16 g_Wt2hi[SS * HH * HP], g_Wt2lo[SS * HH * HP];
__device__ __nv_bfloat16 g_Wt3hi[SS * DD * HP], g_Wt3lo[SS * DD * HP];
__device__ __nv_bfloat16 g_Wv1hi[HH * DD], g_Wv1lo[HH * DD];
__device__ __nv_bfloat16 g_Wv2hi[HH * HP], g_Wv2lo[HH * HP];
__device__ __nv_bfloat16 g_Wv3hi[HP],      g_Wv3lo[HP];
__device__ float g_S1[HP], g_Q1[HP], g_S2[HP], g_Q2[HP], g_SC[1], g_QC[1];
__device__ unsigned g_barctr, g_done;

// ---------------- PTX helpers ----------------
__device__ __forceinline__ uint32_t smem_u32(const void* p) {
    uint32_t a;
    asm("{ .reg .u64 t; cvta.to.shared.u64 t, %1; cvt.u32.u64 %0, t; }" : "=r"(a) : "l"(p));
    return a;
}
#define LDSM4(r, addr) \
    asm volatile("ldmatrix.sync.aligned.m8n8.x4.shared.b16 {%0,%1,%2,%3}, [%4];" \
        : "=r"((r)[0]), "=r"((r)[1]), "=r"((r)[2]), "=r"((r)[3]) : "r"(addr))
#define MMA16816(c, a, b0_, b1_) \
    asm volatile("mma.sync.aligned.m16n8k16.row.col.f32.bf16.bf16.f32 " \
        "{%0,%1,%2,%3}, {%4,%5,%6,%7}, {%8,%9}, {%0,%1,%2,%3};" \
        : "+f"((c)[0]), "+f"((c)[1]), "+f"((c)[2]), "+f"((c)[3]) \
        : "r"((a)[0]), "r"((a)[1]), "r"((a)[2]), "r"((a)[3]), "r"(b0_), "r"(b1_))
#define CP16(dst, src) \
    asm volatile("cp.async.ca.shared.global [%0], [%1], 16;" :: "r"(dst), "l"(src) : "memory")
#define CP_COMMIT() asm volatile("cp.async.commit_group;" ::: "memory")
#define CP_WAIT0()  asm volatile("cp.async.wait_group 0;" ::: "memory")

// atomic grid barrier (R13-proven)
__device__ __forceinline__ void gridbar(unsigned& cnt) {
    __syncthreads();
    if (threadIdx.x == 0) {
        __threadfence();
        atomicAdd(&g_barctr, 1u);
        unsigned target = (++cnt) * NCTA;
        while (*(volatile unsigned*)&g_barctr < target) { }
        __threadfence();
    }
    __syncthreads();
}

// ---------------- transpose + split (weights hi+lo) ----------------
__device__ void tsplit(const float* __restrict__ src, int K, int N,
                       __nv_bfloat16* __restrict__ dh, __nv_bfloat16* __restrict__ dl,
                       int ldT, float (*ts)[33]) {
    int ktiles = (ldT + 31) >> 5, ntiles = (N + 31) >> 5;
    for (int t = 0; t < ktiles * ntiles; t++) {
        int kt = t / ntiles, nt = t - kt * ntiles;
        int k0 = kt << 5, n0 = nt << 5;
        __syncthreads();
        #pragma unroll
        for (int s2 = 0; s2 < 2; s2++) {
            int idx = s2 * NT + threadIdx.x;
            int r = idx >> 5, c = idx & 31;
            int k = k0 + r, n = n0 + c;
            ts[r][c] = (k < K && n < N) ? src[(size_t)k * N + n] : 0.f;
        }
        __syncthreads();
        #pragma unroll
        for (int s2 = 0; s2 < 2; s2++) {
            int idx = s2 * NT + threadIdx.x;
            int rr = idx >> 5, cc = idx & 31;
            int n = n0 + rr, k = k0 + cc;
            if (n < N && k < ldT) {
                float v = ts[cc][rr];
                __nv_bfloat16 hb = __float2bfloat16(v);
                dh[(size_t)n * ldT + k] = hb;
                dl[(size_t)n * ldT + k] = __float2bfloat16(v - __bfloat162float(hb));
            }
        }
    }
}

// ---------------- HMMA GEMM phase (128x32 tile, bf16 activations) ----------
// MODE 0: bf16 C + col stats. MODE 1: fused SDE X/V update + X bf16. MODE 2: N=1 head.
template<int MODE, bool BN>
__device__ __noinline__ void mma_gemm(char* alp, uint32_t sbase,
    int rowBase, int cb,
    const __nv_bfloat16* __restrict__ Abf, int ldA, int K, int Ksteps,
    const __nv_bfloat16* __restrict__ Bh, const __nv_bfloat16* __restrict__ Bl, int Nout,
    const float* __restrict__ bias,
    const float* __restrict__ bng, const float* __restrict__ bnb,
    const float* __restrict__ ssum, const float* __restrict__ ssq,
    __nv_bfloat16* __restrict__ C, int ldc, float* osum, float* osq,
    float hstep, float cstep, float* __restrict__ V,
    float* __restrict__ X, const float* __restrict__ dWi, const float* __restrict__ lawi)
{
    const int tid = threadIdx.x;
    const int lane = tid & 31;
    const int warp = tid >> 5;
    const int mr = warp & 7;
    const int nc = warp >> 3;
    float* scK = (float*)(alp + OF_SC);
    float* shK = (float*)(alp + OF_SH);

    const int ng = Ksteps >> 3;           // 8-half groups per row (32 or 34)
    const int nk16 = Ksteps >> 4;         // 16 or 17
    const int nch = (Ksteps + KC - 1) / KC;
    const int arow = tid >> 2, akq = tid & 3;

    // ---- prologue: full-A + B chunk0 loads; BN table overlaps them ----
    {
        const __nv_bfloat16* asrc = Abf + (size_t)(rowBase + arow) * ldA;
        for (int kg = akq; kg < ng; kg += 4)
            CP16(sbase + OF_A + (uint32_t)(arow * 280 + kg * 8) * 2u, asrc + kg * 8);
    }
    {
        if (tid < 384) {
            int row = tid / 12, kg = tid - row * 12;
            int gk = kg * 8;
            int n = cb + row;
            uint32_t off = (uint32_t)(row * 104 + kg * 8) * 2u;
            uint32_t d0 = sbase + BBUF(0) + off;
            if (gk < Ksteps && n < Nout) {
                CP16(d0, Bh + (size_t)n * Ksteps + gk);
                CP16(d0 + BLO, Bl + (size_t)n * Ksteps + gk);
            } else {
                uint4 z = make_uint4(0, 0, 0, 0);
                *(uint4*)(alp + BBUF(0) + off) = z;
                *(uint4*)(alp + BBUF(0) + BLO + off) = z;
            }
        }
    }
    CP_COMMIT();
    if (BN) {
        const float invB = 1.f / (float)BB;
        for (int k = tid; k < HP; k += NT) {
            if (k < K) {
                float mu  = ssum[k] * invB;
                float var = ssq[k] * invB - mu * mu;
                float rstd = rsqrtf(var + EPSBN);
                float sc = bng[k] * rstd;
                scK[k] = sc; shK[k] = bnb[k] - mu * sc;
            } else { scK[k] = 0.f; shK[k] = 0.f; }
        }
    }
    CP_WAIT0();
    __syncthreads();

    // ---- in-place BN+ReLU on the A tile ----
    if (BN) {
        for (int kg = akq; kg < ng; kg += 4) {
            char* p = alp + OF_A + (uint32_t)(arow * 280 + kg * 8) * 2u;
            union { __nv_bfloat16 h[8]; uint4 u; } t;
            t.u = *(uint4*)p;
            #pragma unroll
            for (int e = 0; e < 8; e++) {
                float v = __bfloat162float(t.h[e]);
                v = fmaxf(fmaf(v, scK[kg * 8 + e], shK[kg * 8 + e]), 0.f);
                t.h[e] = __float2bfloat16(v);
            }
            *(uint4*)p = t.u;
        }
        __syncthreads();
    }

    // ---- main loop: B chunks of KC, A fully resident ----
    auto cpB = [&](int ch, int buf) {
        if (tid < 384) {
            const int k0 = ch * KC;
            int row = tid / 12, kg = tid - row * 12;
            int gk = k0 + kg * 8;
            int n = cb + row;
            uint32_t off = (uint32_t)(row * 104 + kg * 8) * 2u;
            uint32_t d0 = sbase + BBUF(buf) + off;
            if (gk < Ksteps && n < Nout) {
                CP16(d0, Bh + (size_t)n * Ksteps + gk);
                CP16(d0 + BLO, Bl + (size_t)n * Ksteps + gk);
            } else {
                uint4 z = make_uint4(0, 0, 0, 0);
                *(uint4*)(alp + BBUF(buf) + off) = z;
                *(uint4*)(alp + BBUF(buf) + BLO + off) = z;
            }
        }
    };

    float acc[2][4] = {};
    uint32_t ahf[2][4], bhf[2][4], blf[2][4];
    const uint32_t aoOff = sbase + OF_A +
        2u * (uint32_t)((mr * 16 + (lane & 15)) * 280 + ((lane >> 4) << 3));
    const uint32_t boOff = 2u * (uint32_t)((nc * 16 + (lane & 7) + ((lane >> 3) & 1) * 8) * 104
                                           + ((lane >> 4) << 3));

    for (int ch = 0; ch < nch; ch++) {
        const int buf = ch & 1;
        const bool more = (ch + 1 < nch);
        if (more) { cpB(ch + 1, buf ^ 1); CP_COMMIT(); }

        int ns = nk16 - ch * (KC / 16); if (ns > KC / 16) ns = KC / 16;
        uint32_t ao = aoOff + (uint32_t)(ch * (KC / 16)) * 32u;
        uint32_t bo = sbase + BBUF(buf) + boOff;
        LDSM4(ahf[0], ao); LDSM4(bhf[0], bo); LDSM4(blf[0], bo + BLO);
        for (int kk = 0; kk < ns; kk++) {
            const int p = kk & 1;
            if (kk + 1 < ns) {
                uint32_t a2 = ao + (kk + 1) * 32, b2 = bo + (kk + 1) * 32;
                LDSM4(ahf[p ^ 1], a2); LDSM4(bhf[p ^ 1], b2); LDSM4(blf[p ^ 1], b2 + BLO);
            }
            #pragma unroll
            for (int t = 0; t < 2; t++) {
                MMA16816(acc[t], ahf[p], bhf[p][t], bhf[p][t + 2]);
                MMA16816(acc[t], ahf[p], blf[p][t], blf[p][t + 2]);
            }
        }
        CP_WAIT0();
        __syncthreads();
    }

    // ---- fragments -> Cs [128][36] (aliases A region; mma done) ----
    float* Cs = (float*)alp;
    {
        int r0 = mr * 16 + (lane >> 2);
        #pragma unroll
        for (int t = 0; t < 2; t++) {
            int cl = nc * 16 + t * 8 + (lane & 3) * 2;
            Cs[r0 * 36 + cl]           = acc[t][0];
            Cs[r0 * 36 + cl + 1]       = acc[t][1];
            Cs[(r0 + 8) * 36 + cl]     = acc[t][2];
            Cs[(r0 + 8) * 36 + cl + 1] = acc[t][3];
        }
    }
    __syncthreads();

    if (MODE == 0) {
        float* red2 = (float*)(alp + 20480);
        // biased values: write bf16 C, accumulate stats from fp32
        #pragma unroll
        for (int it = 0; it < 8; it++) {
            int idx = it * NT + tid;
            int row = idx >> 5, col = idx & 31;
            int gn = cb + col;
            if (gn < Nout) {
                float v = Cs[row * 36 + col] + bias[gn];
                C[(size_t)(rowBase + row) * ldc + gn] = __float2bfloat16(v);
                Cs[row * 36 + col] = v;
            } else Cs[row * 36 + col] = 0.f;
        }
        __syncthreads();
        {
            int col = tid & 31, seg = tid >> 5;
            float s = 0.f, q = 0.f;
            #pragma unroll
            for (int r8 = 0; r8 < 8; r8++) {
                float v = Cs[(seg * 8 + r8) * 36 + col];
                s += v; q += v * v;
            }
            red2[seg * 32 + col] = s;
            red2[512 + seg * 32 + col] = q;
        }
        __syncthreads();
        if (tid < 32) {
            float s = 0.f, q = 0.f;
            #pragma unroll
            for (int g = 0; g < 16; g++) { s += red2[g * 32 + tid]; q += red2[512 + g * 32 + tid]; }
            int gn = cb + tid;
            if (gn < Nout) { atomicAdd(&osum[gn], s); atomicAdd(&osq[gn], q); }
        }
        __syncthreads();
    } else if (MODE == 1) {
        int row = tid >> 2, quad = tid & 3;
        size_t rbo = (size_t)(rowBase + row) * DD + cb + quad * 8;
        float p1 = 0.f, p2 = 0.f, p3 = 0.f;
        float xr[8];
        #pragma unroll
        for (int j4 = 0; j4 < 2; j4++) {
            int cl = quad * 8 + j4 * 4;
            int gc = cb + cl;
            float4 bj = *(const float4*)(bias + gc);
            float4 xv = *(const float4*)(X + rbo + j4 * 4);
            float4 dv = *(const float4*)(dWi + rbo + j4 * 4);
            float4 lw = *(const float4*)(lawi + gc);
            float q0 = Cs[row * 36 + cl]     + bj.x;
            float q1 = Cs[row * 36 + cl + 1] + bj.y;
            float q2 = Cs[row * 36 + cl + 2] + bj.z;
            float q3 = Cs[row * 36 + cl + 3] + bj.w;
            float n0 = cstep * dv.x, n1 = cstep * dv.y;
            float n2 = cstep * dv.z, n3 = cstep * dv.w;
            float d0 = xv.x - lw.x, d1 = xv.y - lw.y;
            float d2 = xv.z - lw.z, d3 = xv.w - lw.w;
            p1 += d0 * d0 + d1 * d1 + d2 * d2 + d3 * d3;
            p2 += q0 * q0 + q1 * q1 + q2 * q2 + q3 * q3;
            p3 += q0 * n0 + q1 * n1 + q2 * n2 + q3 * n3;
            float4 xo;
            xo.x = xv.x - q0 * hstep + n0;
            xo.y = xv.y - q1 * hstep + n1;
            xo.z = xv.z - q2 * hstep + n2;
            xo.w = xv.w - q3 * hstep + n3;
            *(float4*)(X + rbo + j4 * 4) = xo;
            xr[j4*4+0] = xo.x; xr[j4*4+1] = xo.y; xr[j4*4+2] = xo.z; xr[j4*4+3] = xo.w;
        }
        {
            union { __nv_bfloat16 h[8]; uint4 u; } th;
            #pragma unroll
            for (int e = 0; e < 8; e++) th.h[e] = __float2bfloat16(xr[e]);
            *(uint4*)(g_Xhi + rbo) = th.u;
        }
        float t = -0.5f * hstep * (p1 + p2) + p3;
        t += __shfl_down_sync(0xffffffffu, t, 1);
        t += __shfl_down_sync(0xffffffffu, t, 2);
        if ((lane & 3) == 0) atomicAdd(&V[rowBase + row], t);
        __syncthreads();
    } else {
        if (tid < 128) {
            float v = Cs[tid * 36] + bias[0];
            g_Yv3[rowBase + tid] = v;
            float s = v, q = v * v;
            #pragma unroll
            for (int o = 16; o > 0; o >>= 1) {
                s += __shfl_down_sync(0xffffffffu, s, o);
                q += __shfl_down_sync(0xffffffffu, q, o);
            }
            if ((tid & 31) == 0) { atomicAdd(&g_SC[0], s); atomicAdd(&g_QC[0], q); }
        }
        __syncthreads();
    }
}

// ---------------- single persistent kernel ----------------
extern "C" __global__ void __launch_bounds__(NT, 1)
mega_kernel(const float* __restrict__ x, const float* __restrict__ dW,
            const float* __restrict__ law, const float* __restrict__ tg,
            const float* __restrict__ W1, const float* __restrict__ b1,
            const float* __restrict__ g1, const float* __restrict__ be1,
            const float* __restrict__ W2, const float* __restrict__ b2,
            const float* __restrict__ g2, const float* __restrict__ be2,
            const float* __restrict__ W3, const float* __restrict__ b3,
            const float* __restrict__ Wv1, const float* __restrict__ bv1,
            const float* __restrict__ gv1, const float* __restrict__ bev1,
            const float* __restrict__ Wv2, const float* __restrict__ bv2,
            const float* __restrict__ gv2, const float* __restrict__ bev2,
            const float* __restrict__ Wv3, const float* __restrict__ bv3,
            const float* __restrict__ gv3, const float* __restrict__ bev3,
            float* __restrict__ V)
{
    extern __shared__ char dsm[];
    const int cta = blockIdx.x;
    const int tid = threadIdx.x;
    char* alp = dsm;
    uint32_t sbase = smem_u32(dsm);
    unsigned bar = 0;
    const int rb = (cta & 15) * 128;
    const int cb = (cta >> 4) * 32;

    if (cta == 0) {
        for (int j = tid; j < HP; j += NT) { g_S1[j] = 0.f; g_Q1[j] = 0.f; g_S2[j] = 0.f; g_Q2[j] = 0.f; }
        if (tid == 0) { g_SC[0] = 0.f; g_QC[0] = 0.f; }
    }
    {   // copy X fp32 + bf16
        for (int idx = cta * NT + tid; idx < BB * DD / 4; idx += NCTA * NT)
            ((float4*)g_X)[idx] = ((const float4*)x)[idx];
        int idx8 = cta * NT + tid;
        if (idx8 < BB * DD / 8) {
            const float* xp = x + idx8 * 8;
            union { __nv_bfloat16 h[8]; uint4 u; } th;
            #pragma unroll
            for (int e = 0; e < 8; e++) th.h[e] = __float2bfloat16(xp[e]);
            *(uint4*)(g_Xhi + (size_t)idx8 * 8) = th.u;
        }
    }
    {
        float (*ts)[33] = (float (*)[33])alp;
        for (int m = cta; m < 153; m += NCTA) {
            if (m < 50)
                tsplit(W1 + (size_t)m * DD * HH, DD, HH,
                       g_Wt1hi + (size_t)m * HH * DD, g_Wt1lo + (size_t)m * HH * DD, DD, ts);
            else if (m < 100)
                tsplit(W2 + (size_t)(m - 50) * HH * HH, HH, HH,
                       g_Wt2hi + (size_t)(m - 50) * HH * HP, g_Wt2lo + (size_t)(m - 50) * HH * HP, HP, ts);
            else if (m < 150)
                tsplit(W3 + (size_t)(m - 100) * HH * DD, HH, DD,
                       g_Wt3hi + (size_t)(m - 100) * DD * HP, g_Wt3lo + (size_t)(m - 100) * DD * HP, HP, ts);
            else if (m == 150) tsplit(Wv1, DD, HH, g_Wv1hi, g_Wv1lo, DD, ts);
            else if (m == 151) tsplit(Wv2, HH, HH, g_Wv2hi, g_Wv2lo, HP, ts);
            else               tsplit(Wv3, HH, 1,  g_Wv3hi, g_Wv3lo, HP, ts);
        }
    }
    gridbar(bar);

    // v0 L1
    if (cta < 144)
        mma_gemm<0, false>(alp, sbase, rb, cb,
            g_Xhi, DD, 256, 256, g_Wv1hi, g_Wv1lo, HH, bv1,
            0, 0, 0, 0, g_Y1b, HP, g_S1, g_Q1, 0, 0, 0, 0, 0, 0);
    gridbar(bar);
    // v0 L2
    if (cta < 144)
        mma_gemm<0, true>(alp, sbase, rb, cb,
            g_Y1b, HP, 266, 272, g_Wv2hi, g_Wv2lo, HH, bv2,
            gv1, bev1, g_S1, g_Q1, g_Y2b, HP, g_S2, g_Q2, 0, 0, 0, 0, 0, 0);
    gridbar(bar);
    // v0 L3 (N=1)
    if (cta < 16)
        mma_gemm<2, true>(alp, sbase, cta * 128, 0,
            g_Y2b, HP, 266, 272, g_Wv3hi, g_Wv3lo, 1, bv3,
            gv2, bev2, g_S2, g_Q2, 0, 0, 0, 0, 0, 0, 0, 0, 0, 0);
    else if (cta == 100)
        for (int j = tid; j < HP; j += NT) { g_S1[j] = 0.f; g_Q1[j] = 0.f; }
    gridbar(bar);
    // v0 finalize
    {
        int r = cta * NT + tid;
        if (r < BB) {
            float invB = 1.f / (float)BB;
            float mu  = g_SC[0] * invB;
            float var = g_QC[0] * invB - mu * mu;
            float rstd = rsqrtf(var + EPSBN);
            V[r] = fmaxf(gv3[0] * (g_Yv3[r] - mu) * rstd + bev3[0], 0.f);
        }
        if (cta == 8)
            for (int j = tid; j < HP; j += NT) { g_S2[j] = 0.f; g_Q2[j] = 0.f; }
    }
    gridbar(bar);

    #pragma unroll 1
    for (int i = 0; i < SS; i++) {
        float h  = tg[i + 1] - tg[i];
        float cs = SIGMA_C * sqrtf(h);
        // L1: Xbf16 -> Y1b + S1/Q1
        if (cta < 144)
            mma_gemm<0, false>(alp, sbase, rb, cb,
                g_Xhi, DD, 256, 256,
                g_Wt1hi + (size_t)i * HH * DD, g_Wt1lo + (size_t)i * HH * DD, HH,
                b1 + (size_t)i * HH, 0, 0, 0, 0,
                g_Y1b, HP, g_S1, g_Q1, 0, 0, 0, 0, 0, 0);
        else if (cta == 147)
            for (int j = tid; j < HP; j += NT) { g_S2[j] = 0.f; g_Q2[j] = 0.f; }
        gridbar(bar);
        // L2: BN(Y1b) -> Y2b + S2/Q2
        if (cta < 144)
            mma_gemm<0, true>(alp, sbase, rb, cb,
                g_Y1b, HP, 266, 272,
                g_Wt2hi + (size_t)i * HH * HP, g_Wt2lo + (size_t)i * HH * HP, HH,
                b2 + (size_t)i * HH, g1 + (size_t)i * HH, be1 + (size_t)i * HH, g_S1, g_Q1,
                g_Y2b, HP, g_S2, g_Q2, 0, 0, 0, 0, 0, 0);
        gridbar(bar);
        // L3: BN(Y2b) -> grad; fused SDE update + X bf16
        if (cta < 128)
            mma_gemm<1, true>(alp, sbase, rb, cb,
                g_Y2b, HP, 266, 272,
                g_Wt3hi + (size_t)i * DD * HP, g_Wt3lo + (size_t)i * DD * HP, DD,
                b3 + (size_t)i * DD, g2 + (size_t)i * HH, be2 + (size_t)i * HH, g_S2, g_Q2,
                0, 0, 0, 0, h, cs, V, g_X, dW + (size_t)i * BB * DD, law + (size_t)i * DD);
        else if (cta == 144)
            for (int j = tid; j < HP; j += NT) { g_S1[j] = 0.f; g_Q1[j] = 0.f; }
        gridbar(bar);
    }

    if (tid == 0) {
        __threadfence();
        atomicAdd(&g_done, 1u);
        if (cta == 0) {
            while (*(volatile unsigned*)&g_done < NCTA) { }
            g_barctr = 0u;
            __threadfence();
            g_done = 0u;
        }
    }
}

// ---------------- host launcher ----------------
extern "C" void kernel_launch(void* const* d_in, const int* in_sizes, int n_in,
                              void* d_out, int out_size)
{
    cudaFuncSetAttribute((const void*)mega_kernel,
                         cudaFuncAttributeMaxDynamicSharedMemorySize, SMEM_DYN);
    mega_kernel<<<NCTA, NT, SMEM_DYN>>>(
        (const float*)d_in[0], (const float*)d_in[1], (const float*)d_in[2], (const float*)d_in[3],
        (const float*)d_in[4],  (const float*)d_in[5],  (const float*)d_in[6],  (const float*)d_in[7],
        (const float*)d_in[8],  (const float*)d_in[9],  (const float*)d_in[10], (const float*)d_in[11],
        (const float*)d_in[12], (const float*)d_in[13],
        (const float*)d_in[14], (const float*)d_in[15], (const float*)d_in[16], (const float*)d_in[17],
        (const float*)d_in[18], (const float*)d_in[19], (const float*)d_in[20], (const float*)d_in[21],
        (const float*)d_in[22], (const float*)d_in[23], (const float*)d_in[24], (const float*)d_in[25],
        (float*)d_out);
    (void)in_sizes; (void)n_in; (void)out_size;
}